// round 7
// baseline (speedup 1.0000x reference)
#include <cuda_runtime.h>
#include <cuda_bf16.h>
#include <math.h>

#define B_ 8
#define C_ 64
#define H_ 128
#define W_ 128
#define HS 256
#define WS 256
#define NP (B_ * H_ * W_)      // 131072
#define NP4 (NP / 4)           // 32768

__device__ float g_meanp[8 * NP];
__device__ float g_mean[NP];

// ---------------------------------------------------------------------------
// packed f32x2 helpers
// ---------------------------------------------------------------------------
__device__ __forceinline__ unsigned long long pack2(float lo, float hi)
{
    unsigned long long r;
    asm("mov.b64 %0, {%1, %2};" : "=l"(r) : "f"(lo), "f"(hi));
    return r;
}
__device__ __forceinline__ float2 unpack2(unsigned long long v)
{
    float lo, hi;
    asm("mov.b64 {%0, %1}, %2;" : "=f"(lo), "=f"(hi) : "l"(v));
    return make_float2(lo, hi);
}
#define FMA2(acc, ww, tt) \
    asm("fma.rn.f32x2 %0, %1, %2, %0;" : "+l"(acc) : "l"(ww), "l"(tt))

// ---------------------------------------------------------------------------
// K1a: partial channel sums. 8 channel groups x 8 channels.
// ---------------------------------------------------------------------------
__global__ void mean_partial_kernel(const float* __restrict__ x,
                                    float4* __restrict__ mp4)
{
    int t = blockIdx.x * blockDim.x + threadIdx.x;
    int cg   = t >> 15;
    int idx4 = t & (NP4 - 1);
    int b  = idx4 >> 12;
    int p4 = idx4 & 4095;
    const float4* px = (const float4*)(x + ((size_t)b << 20) + ((size_t)(cg * 8) << 14)) + p4;
    float4 s = make_float4(0.f, 0.f, 0.f, 0.f);
#pragma unroll
    for (int c = 0; c < 8; c++) {
        float4 v = px[(size_t)c << 12];
        s.x += v.x; s.y += v.y; s.z += v.z; s.w += v.w;
    }
    mp4[t] = s;
}

__global__ void mean_reduce_kernel(const float4* __restrict__ mp4,
                                   float4* __restrict__ mean4)
{
    int i = blockIdx.x * blockDim.x + threadIdx.x;
    if (i >= NP4) return;
    float sx = 0.f, sy = 0.f, sz = 0.f, sw_ = 0.f;
#pragma unroll
    for (int g = 0; g < 8; g++) {
        float4 v = mp4[g * NP4 + i];
        sx += v.x; sy += v.y; sz += v.z; sw_ += v.w;
    }
    mean4[i] = make_float4(sx * (1.f / 64.f), sy * (1.f / 64.f),
                           sz * (1.f / 64.f), sw_ * (1.f / 64.f));
}

// ---------------------------------------------------------------------------
// K2: fused weights + CARAFE, contiguous stores.
// Block = 128 thr = 4 warps = (2 column halves) x (2 channel halves),
// covering ONE low-res row. Lane = 2 low-res cols (float2 loads), computes
// BOTH hi-res sub-rows. Each hi-res row stored as ONE STG.128/lane at
// byte offset 16*lane -> warp-contiguous 512B, full sectors (no RMW).
// ---------------------------------------------------------------------------
__global__ void __launch_bounds__(128, 4) carafe_fused_kernel(
    const float* __restrict__ x,
    const float* __restrict__ mean,
    const float* __restrict__ w_off,
    const float* __restrict__ b_off,
    float* __restrict__ out)
{
    // collapsed 5x5 conv -> 9 warp-uniform coeffs per (ir,j), per out-channel
    __shared__ float sc0[2][2][9];
    __shared__ float sc1[2][2][9];
    __shared__ float sbias[2];
    if (threadIdx.x < 4) {
        int ir = threadIdx.x >> 1, j = threadIdx.x & 1;
        float a0[9], a1[9];
#pragma unroll
        for (int k = 0; k < 9; k++) { a0[k] = 0.f; a1[k] = 0.f; }
#pragma unroll
        for (int pp = 0; pp < 5; pp++)
#pragma unroll
            for (int qq = 0; qq < 5; qq++) {
                int k = (((ir + pp - 2) >> 1) + 1) * 3 + (((j + qq - 2) >> 1) + 1);
                a0[k] += w_off[pp * 5 + qq];
                a1[k] += w_off[25 + pp * 5 + qq];
            }
#pragma unroll
        for (int k = 0; k < 9; k++) { sc0[ir][j][k] = a0[k]; sc1[ir][j][k] = a1[k]; }
    }
    if (threadIdx.x < 2) sbias[threadIdx.x] = b_off[threadIdx.x];
    __syncthreads();

    int by = blockIdx.x;               // 0..1023 : (b, y)
    int b = by >> 7, y = by & 127;
    int warp = threadIdx.x >> 5;
    int lane = threadIdx.x & 31;
    int h  = warp & 1;                 // column half
    int cg = warp >> 1;                // channel half
    int X  = 64 * h + 2 * lane;        // low-res col of this lane's pixel 0

    bool hasN = (y > 0), hasS = (y < H_ - 1);

    // ---- mean window: rows y-1..y+1, cols X-1..X+2 ----
    const float* mb = mean + ((size_t)b << 14);
    float mrow[3][4];
#pragma unroll
    for (int r = 0; r < 3; r++) {
        int yy = y - 1 + r;
        bool ok = (yy >= 0 && yy < H_);
        float2 q = ok ? *(const float2*)(mb + yy * W_ + X) : make_float2(0.f, 0.f);
        float lf = __shfl_up_sync(0xffffffffu, q.y, 1);
        float rt = __shfl_down_sync(0xffffffffu, q.x, 1);
        if (lane == 0)  lf = (h && ok) ? mb[yy * W_ + 63] : 0.f;
        if (lane == 31) rt = (!h && ok) ? mb[yy * W_ + 64] : 0.f;
        mrow[r][0] = lf; mrow[r][1] = q.x; mrow[r][2] = q.y; mrow[r][3] = rt;
    }

    // ---- weights for pixels X, X+1; both sub-rows; packed over pixel pair ----
    unsigned long long wp[2][2][9];    // [ir][j][k] = {w_pix0, w_pix1}
    {
        float lo[36];                  // pixel-0 weights, [ir*2+j][9]
#pragma unroll
        for (int p = 0; p < 2; p++) {
            float m0[9];
#pragma unroll
            for (int r = 0; r < 3; r++)
#pragma unroll
                for (int c = 0; c < 3; c++) m0[r * 3 + c] = mrow[r][p + c];
            float g9[9];
            float mc = m0[4];
#pragma unroll
            for (int k = 0; k < 9; k++) {
                float d = m0[k] - mc;
                g9[k] = __fdividef(1.0f, d * d + 1.0f);
            }
#pragma unroll
            for (int ir = 0; ir < 2; ir++)
#pragma unroll
                for (int j = 0; j < 2; j++) {
                    float o0 = 0.f, o1 = 0.f;
#pragma unroll
                    for (int k = 0; k < 9; k++) {
                        o0 = fmaf(m0[k], sc0[ir][j][k], o0);
                        o1 = fmaf(m0[k], sc1[ir][j][k], o1);
                    }
                    float s0 = (ir ? 0.25f : -0.25f) + 0.25f * tanhf(o0 + sbias[0]);
                    float s1 = (j  ? 0.25f : -0.25f) + 0.25f * tanhf(o1 + sbias[1]);
                    float lv[9];
                    float sum = 0.f;
#pragma unroll
                    for (int k = 0; k < 9; k++) {
                        float d0 = s0 - (float)(k / 3 - 1);
                        float d1 = s1 - (float)(k % 3 - 1);
                        float ker = __fdividef(1.0f, d0 * d0 + d1 * d1 + 0.5f);
                        lv[k] = __expf(g9[k] * ker);   // arg in (0,2]
                        sum += lv[k];
                    }
                    float inv = __fdividef(1.0f, sum);
                    if (p == 0) {
#pragma unroll
                        for (int k = 0; k < 9; k++)
                            lo[(ir * 2 + j) * 9 + k] = lv[k] * inv;
                    } else {
#pragma unroll
                        for (int k = 0; k < 9; k++)
                            wp[ir][j][k] = pack2(lo[(ir * 2 + j) * 9 + k], lv[k] * inv);
                    }
                }
        }
    }

    // ---- CARAFE channel loop (32 channels for this warp's half) ----
    const float* xb = x + ((size_t)b << 20) + ((size_t)(cg * 32) << 14) + y * W_ + X;
    float* ob = out + ((size_t)(b * C_ + cg * 32)) * (HS * WS)
                    + (size_t)(2 * y) * WS + 128 * h + 4 * lane;

    int hoff = h ? -1 : 2;    // seam-halo column offset (warp-uniform)

#pragma unroll 1
    for (int c = 0; c < 32; c++) {
        const float* p0 = xb + ((size_t)c << 14);
        float2 q0 = hasN ? *(const float2*)(p0 - W_) : make_float2(0.f, 0.f);
        float2 q1 = *(const float2*)p0;
        float2 q2 = hasS ? *(const float2*)(p0 + W_) : make_float2(0.f, 0.f);

        // seam-halo candidates: interior cols, valid for ALL lanes
        float c0 = hasN ? p0[hoff - W_] : 0.f;
        float c1 = p0[hoff];
        float c2 = hasS ? p0[hoff + W_] : 0.f;

        float lf0 = __shfl_up_sync(0xffffffffu, q0.y, 1);
        float lf1 = __shfl_up_sync(0xffffffffu, q1.y, 1);
        float lf2 = __shfl_up_sync(0xffffffffu, q2.y, 1);
        float rt0 = __shfl_down_sync(0xffffffffu, q0.x, 1);
        float rt1 = __shfl_down_sync(0xffffffffu, q1.x, 1);
        float rt2 = __shfl_down_sync(0xffffffffu, q2.x, 1);
        if (h) {            // warp-uniform branch
            if (lane == 0)  { lf0 = c0; lf1 = c1; lf2 = c2; }
            if (lane == 31) { rt0 = 0.f; rt1 = 0.f; rt2 = 0.f; }
        } else {
            if (lane == 0)  { lf0 = 0.f; lf1 = 0.f; lf2 = 0.f; }
            if (lane == 31) { rt0 = c0; rt1 = c1; rt2 = c2; }
        }

        // packed tap pairs per row: {tap for pix0, tap for pix1}
        unsigned long long tp[3][3];
        tp[0][0] = pack2(lf0, q0.x); tp[0][1] = pack2(q0.x, q0.y); tp[0][2] = pack2(q0.y, rt0);
        tp[1][0] = pack2(lf1, q1.x); tp[1][1] = pack2(q1.x, q1.y); tp[1][2] = pack2(q1.y, rt1);
        tp[2][0] = pack2(lf2, q2.x); tp[2][1] = pack2(q2.x, q2.y); tp[2][2] = pack2(q2.y, rt2);

        unsigned long long acc[2][2] = {{0ull, 0ull}, {0ull, 0ull}};
#pragma unroll
        for (int r = 0; r < 3; r++)
#pragma unroll
            for (int cc = 0; cc < 3; cc++) {
                int k = r * 3 + cc;
                unsigned long long t = tp[r][cc];
                FMA2(acc[0][0], wp[0][0][k], t);
                FMA2(acc[0][1], wp[0][1][k], t);
                FMA2(acc[1][0], wp[1][0][k], t);
                FMA2(acc[1][1], wp[1][1][k], t);
            }

        float2 a00 = unpack2(acc[0][0]), a01 = unpack2(acc[0][1]);
        float2 a10 = unpack2(acc[1][0]), a11 = unpack2(acc[1][1]);

        float* orow = ob + (size_t)c * (HS * WS);
        __stcs((float4*)orow,        make_float4(a00.x, a01.x, a00.y, a01.y));
        __stcs((float4*)(orow + WS), make_float4(a10.x, a11.x, a10.y, a11.y));
    }
}

extern "C" void kernel_launch(void* const* d_in, const int* in_sizes, int n_in,
                              void* d_out, int out_size)
{
    const float* x     = (const float*)d_in[0];   // [8,64,128,128]
    const float* w_off = (const float*)d_in[1];   // [2,1,5,5]
    const float* b_off = (const float*)d_in[2];   // [2]
    float* out = (float*)d_out;                   // [8,64,256,256]

    float* mp;
    float* mean;
    cudaGetSymbolAddress((void**)&mp, g_meanp);
    cudaGetSymbolAddress((void**)&mean, g_mean);

    mean_partial_kernel<<<(8 * NP4) / 256, 256>>>(x, (float4*)mp);
    mean_reduce_kernel<<<NP4 / 256, 256>>>((const float4*)mp, (float4*)mean);
    carafe_fused_kernel<<<B_ * H_, 128>>>(x, mean, w_off, b_off, out);
}

// round 8
// speedup vs baseline: 1.2974x; 1.2974x over previous
#include <cuda_runtime.h>
#include <cuda_bf16.h>
#include <math.h>

#define B_ 8
#define C_ 64
#define H_ 128
#define W_ 128
#define HS 256
#define WS 256

// ---------------------------------------------------------------------------
// packed f32x2 helpers
// ---------------------------------------------------------------------------
__device__ __forceinline__ unsigned long long pack2(float lo, float hi)
{
    unsigned long long r;
    asm("mov.b64 %0, {%1, %2};" : "=l"(r) : "f"(lo), "f"(hi));
    return r;
}
__device__ __forceinline__ float2 unpack2(unsigned long long v)
{
    float lo, hi;
    asm("mov.b64 {%0, %1}, %2;" : "=f"(lo), "=f"(hi) : "l"(v));
    return make_float2(lo, hi);
}
#define FMA2(acc, ww, tt) \
    asm("fma.rn.f32x2 %0, %1, %2, %0;" : "+l"(acc) : "l"(ww), "l"(tt))

__device__ __forceinline__ float4 ldg4_or_zero(const float* p, bool pred)
{
    if (pred) return *(const float4*)p;
    return make_float4(0.f, 0.f, 0.f, 0.f);
}

// ---------------------------------------------------------------------------
// Single fused kernel: in-block channel mean -> weights -> CARAFE.
// Block = 128 thr = 4 warps. Block covers low-res rows y0, y0+1.
//   Phase 1: warp r computes mean of row y0-1+r (64-ch sum, float4/lane),
//            writes smem row with zero halos. (Also primes L2 with x.)
//   Phase 2: warp (dy, ir) computes weights for row y0+dy, sub-row ir,
//            from smem means; then R6 main loop: 3x LDG.128 + shuffles +
//            packed f32x2 FMAs + 2x stcs STG.128 per channel.
// ---------------------------------------------------------------------------
__global__ void __launch_bounds__(128, 4) carafe_full_kernel(
    const float* __restrict__ x,
    const float* __restrict__ w_off,
    const float* __restrict__ b_off,
    float* __restrict__ out)
{
    __shared__ float sm[4][132];        // mean rows y0-1..y0+2, col index +1
    __shared__ float sc0[2][2][9];      // collapsed 5x5 conv coeffs, out-ch 0
    __shared__ float sc1[2][2][9];      // out-ch 1
    __shared__ float sbias[2];

    if (threadIdx.x < 4) {
        int ir = threadIdx.x >> 1, j = threadIdx.x & 1;
        float a0[9], a1[9];
#pragma unroll
        for (int k = 0; k < 9; k++) { a0[k] = 0.f; a1[k] = 0.f; }
#pragma unroll
        for (int pp = 0; pp < 5; pp++)
#pragma unroll
            for (int qq = 0; qq < 5; qq++) {
                int k = (((ir + pp - 2) >> 1) + 1) * 3 + (((j + qq - 2) >> 1) + 1);
                a0[k] += w_off[pp * 5 + qq];
                a1[k] += w_off[25 + pp * 5 + qq];
            }
#pragma unroll
        for (int k = 0; k < 9; k++) { sc0[ir][j][k] = a0[k]; sc1[ir][j][k] = a1[k]; }
    }
    if (threadIdx.x < 2) sbias[threadIdx.x] = b_off[threadIdx.x];

    int b  = blockIdx.x >> 6;
    int y0 = (blockIdx.x & 63) * 2;
    int warp = threadIdx.x >> 5;
    int lane = threadIdx.x & 31;

    // ---- Phase 1: mean rows y0-1 .. y0+2 (one per warp) ----
    {
        int yy = y0 - 1 + warp;
        float4 a0 = make_float4(0.f, 0.f, 0.f, 0.f);
        float4 a1 = make_float4(0.f, 0.f, 0.f, 0.f);
        if (yy >= 0 && yy < H_) {
            const float4* px = (const float4*)(x + ((size_t)b << 20) + yy * W_) + lane;
#pragma unroll
            for (int c = 0; c < C_; c += 2) {
                float4 v0 = px[(size_t)c << 12];
                float4 v1 = px[(size_t)(c + 1) << 12];
                a0.x += v0.x; a0.y += v0.y; a0.z += v0.z; a0.w += v0.w;
                a1.x += v1.x; a1.y += v1.y; a1.z += v1.z; a1.w += v1.w;
            }
        }
        const float inv = 1.0f / 64.0f;
        sm[warp][1 + 4 * lane + 0] = (a0.x + a1.x) * inv;
        sm[warp][1 + 4 * lane + 1] = (a0.y + a1.y) * inv;
        sm[warp][1 + 4 * lane + 2] = (a0.z + a1.z) * inv;
        sm[warp][1 + 4 * lane + 3] = (a0.w + a1.w) * inv;
        if (lane == 0)  sm[warp][0]   = 0.f;
        if (lane == 31) sm[warp][129] = 0.f;
    }
    __syncthreads();

    // ---- Phase 2: weights for this warp's (row, sub-row) ----
    int dy = warp & 1;                 // low-res row within block
    int ir = warp >> 1;                // hi-res sub-row
    int y = y0 + dy;
    bool hasN = (y > 0), hasS = (y < H_ - 1);

    float mrow[3][6];
#pragma unroll
    for (int r = 0; r < 3; r++)
#pragma unroll
        for (int c = 0; c < 6; c++)
            mrow[r][c] = sm[dy + r][4 * lane + c];   // cols 4lane-1 .. 4lane+4

    // weights for pixels 4lane+p (p=0..3), packed over pixel pairs:
    // wp[pp*2+j][k] = {w for pixel 2pp, w for pixel 2pp+1}, j = sub-col
    unsigned long long wp[4][9];
    {
        float lo[18];
#pragma unroll
        for (int p = 0; p < 4; p++) {
            float m0[9];
#pragma unroll
            for (int r = 0; r < 3; r++)
#pragma unroll
                for (int c = 0; c < 3; c++) m0[r * 3 + c] = mrow[r][p + c];
            float g9[9];
            float mc = m0[4];
#pragma unroll
            for (int k = 0; k < 9; k++) {
                float d = m0[k] - mc;
                g9[k] = __fdividef(1.0f, d * d + 1.0f);
            }
            float cur[18];
#pragma unroll
            for (int j = 0; j < 2; j++) {
                float o0 = 0.f, o1 = 0.f;
#pragma unroll
                for (int k = 0; k < 9; k++) {
                    o0 = fmaf(m0[k], sc0[ir][j][k], o0);
                    o1 = fmaf(m0[k], sc1[ir][j][k], o1);
                }
                float s0 = (ir ? 0.25f : -0.25f) + 0.25f * tanhf(o0 + sbias[0]);
                float s1 = (j  ? 0.25f : -0.25f) + 0.25f * tanhf(o1 + sbias[1]);
                float lv[9];
                float sum = 0.f;
#pragma unroll
                for (int k = 0; k < 9; k++) {
                    float d0 = s0 - (float)(k / 3 - 1);
                    float d1 = s1 - (float)(k % 3 - 1);
                    float ker = __fdividef(1.0f, d0 * d0 + d1 * d1 + 0.5f);
                    lv[k] = __expf(g9[k] * ker);   // arg in (0,2]: no max-sub
                    sum += lv[k];
                }
                float sinv = __fdividef(1.0f, sum);
#pragma unroll
                for (int k = 0; k < 9; k++) cur[j * 9 + k] = lv[k] * sinv;
            }
            if ((p & 1) == 0) {
#pragma unroll
                for (int t = 0; t < 18; t++) lo[t] = cur[t];
            } else {
#pragma unroll
                for (int j = 0; j < 2; j++)
#pragma unroll
                    for (int k = 0; k < 9; k++)
                        wp[(p >> 1) * 2 + j][k] = pack2(lo[j * 9 + k], cur[j * 9 + k]);
            }
        }
    }

    // ---- Phase 3: CARAFE channel loop (R6 structure) ----
    const float* xb = x + ((size_t)b << 20) + y * W_ + 4 * lane;
    float* ob = out + (size_t)b * C_ * (HS * WS)
                    + (size_t)(2 * y + ir) * WS + 8 * lane;

#pragma unroll 1
    for (int c = 0; c < C_; c++) {
        const float* p0 = xb + ((size_t)c << 14);
        float vv[3][6];
        {
            float4 q0 = ldg4_or_zero(p0 - W_, hasN);
            float4 q1 = *(const float4*)p0;
            float4 q2 = ldg4_or_zero(p0 + W_, hasS);
            float l0 = __shfl_up_sync(0xffffffffu, q0.w, 1);
            float l1 = __shfl_up_sync(0xffffffffu, q1.w, 1);
            float l2 = __shfl_up_sync(0xffffffffu, q2.w, 1);
            float r0 = __shfl_down_sync(0xffffffffu, q0.x, 1);
            float r1 = __shfl_down_sync(0xffffffffu, q1.x, 1);
            float r2 = __shfl_down_sync(0xffffffffu, q2.x, 1);
            bool z0 = (lane == 0), z31 = (lane == 31);
            vv[0][0] = z0 ? 0.f : l0; vv[1][0] = z0 ? 0.f : l1; vv[2][0] = z0 ? 0.f : l2;
            vv[0][1] = q0.x; vv[0][2] = q0.y; vv[0][3] = q0.z; vv[0][4] = q0.w;
            vv[1][1] = q1.x; vv[1][2] = q1.y; vv[1][3] = q1.z; vv[1][4] = q1.w;
            vv[2][1] = q2.x; vv[2][2] = q2.y; vv[2][3] = q2.z; vv[2][4] = q2.w;
            vv[0][5] = z31 ? 0.f : r0; vv[1][5] = z31 ? 0.f : r1; vv[2][5] = z31 ? 0.f : r2;
        }

        // packed tap pairs: tp[r][cc] covers pixel pair {2pp, 2pp+1} via index 2pp+cc
        unsigned long long tp[3][5];
#pragma unroll
        for (int r = 0; r < 3; r++)
#pragma unroll
            for (int i = 0; i < 5; i++)
                tp[r][i] = pack2(vv[r][i], vv[r][i + 1]);

        unsigned long long acc[2][2] = {{0ull, 0ull}, {0ull, 0ull}};
#pragma unroll
        for (int pp = 0; pp < 2; pp++)
#pragma unroll
            for (int r = 0; r < 3; r++)
#pragma unroll
                for (int cc = 0; cc < 3; cc++) {
                    int k = r * 3 + cc;
                    unsigned long long t = tp[r][2 * pp + cc];
                    FMA2(acc[pp][0], wp[pp * 2 + 0][k], t);
                    FMA2(acc[pp][1], wp[pp * 2 + 1][k], t);
                }

        float2 a00 = unpack2(acc[0][0]), a01 = unpack2(acc[0][1]);
        float2 a10 = unpack2(acc[1][0]), a11 = unpack2(acc[1][1]);

        float* orow = ob + (size_t)c * (HS * WS);
        __stcs((float4*)orow,       make_float4(a00.x, a01.x, a00.y, a01.y));
        __stcs((float4*)(orow + 4), make_float4(a10.x, a11.x, a10.y, a11.y));
    }
}

extern "C" void kernel_launch(void* const* d_in, const int* in_sizes, int n_in,
                              void* d_out, int out_size)
{
    const float* x     = (const float*)d_in[0];   // [8,64,128,128]
    const float* w_off = (const float*)d_in[1];   // [2,1,5,5]
    const float* b_off = (const float*)d_in[2];   // [2]
    float* out = (float*)d_out;                   // [8,64,256,256]

    carafe_full_kernel<<<B_ * H_ / 2, 128>>>(x, w_off, b_off, out);
}